// round 1
// baseline (speedup 1.0000x reference)
#include <cuda_runtime.h>
#include <math.h>

#define BB 1024
#define TT 512
#define II 4
#define HH 32
#define GG 96   // 3*H

// Scratch sequence buffers (allocation-free rule: __device__ globals).
__device__ float g_h1 [(size_t)BB * TT * 2 * HH];  // layer0 output, concat [fwd|bwd]
__device__ float g_out[(size_t)BB * TT * 2 * HH];  // layer1 output, concat [fwd|bwd]

__device__ __forceinline__ float fsigmoid(float x) {
    return 1.0f / (1.0f + __expf(-x));
}

// ---------------------------------------------------------------------------
// Layer 0: input I=4. One warp per (batch, dir). Lane j owns hidden dim j.
// grid: (B/8, 2), block: 256 (8 warps)
// ---------------------------------------------------------------------------
__global__ void __launch_bounds__(256) gru_l0_kernel(
    const float* __restrict__ x,      // [B,T,4]
    const float* __restrict__ w_ih,   // [2,96,4]
    const float* __restrict__ w_hh,   // [2,96,32]
    const float* __restrict__ b_ih,   // [2,96]
    const float* __restrict__ b_hh)   // [2,96]
{
    __shared__ float sWhh[HH][GG];   // transposed: sWhh[k][g]
    __shared__ float sB[2 * GG];

    const int dir = blockIdx.y;
    const int tid = threadIdx.x;

    const float* whh = w_hh + dir * GG * HH;
    for (int idx = tid; idx < GG * HH; idx += 256) {
        int g = idx / HH, k = idx % HH;
        sWhh[k][g] = whh[idx];
    }
    for (int idx = tid; idx < GG; idx += 256) {
        sB[idx]      = b_ih[dir * GG + idx];
        sB[GG + idx] = b_hh[dir * GG + idx];
    }
    __syncthreads();

    const int warp = tid >> 5;
    const int j    = tid & 31;
    const int b    = blockIdx.x * 8 + warp;

    // per-thread input-projection weights (12 regs)
    const float* wih = w_ih + dir * GG * II;
    float wr0 = wih[(j     ) * 4 + 0], wr1 = wih[(j     ) * 4 + 1],
          wr2 = wih[(j     ) * 4 + 2], wr3 = wih[(j     ) * 4 + 3];
    float wz0 = wih[(j + 32) * 4 + 0], wz1 = wih[(j + 32) * 4 + 1],
          wz2 = wih[(j + 32) * 4 + 2], wz3 = wih[(j + 32) * 4 + 3];
    float wn0 = wih[(j + 64) * 4 + 0], wn1 = wih[(j + 64) * 4 + 1],
          wn2 = wih[(j + 64) * 4 + 2], wn3 = wih[(j + 64) * 4 + 3];

    const float br  = sB[j]      + sB[GG + j];
    const float bz  = sB[32 + j] + sB[GG + 32 + j];
    const float bxn = sB[64 + j];
    const float bhn = sB[GG + 64 + j];

    float h = 0.0f;
    const int tstart = dir ? (TT - 1) : 0;
    const int tstep  = dir ? -1 : 1;

    const float* xb = x + (size_t)b * TT * II;
    float* ob = g_h1 + (size_t)b * TT * 2 * HH + dir * HH + j;

    int t = tstart;
    for (int s = 0; s < TT; ++s, t += tstep) {
        float4 xx = __ldg(reinterpret_cast<const float4*>(xb + (size_t)t * 4));

        float r  = br  + wr0 * xx.x + wr1 * xx.y + wr2 * xx.z + wr3 * xx.w;
        float z  = bz  + wz0 * xx.x + wz1 * xx.y + wz2 * xx.z + wz3 * xx.w;
        float xn = bxn + wn0 * xx.x + wn1 * xx.y + wn2 * xx.z + wn3 * xx.w;
        float hn = bhn;

        #pragma unroll
        for (int k = 0; k < HH; k++) {
            float hk = __shfl_sync(0xffffffffu, h, k);
            r  += sWhh[k][j]      * hk;
            z  += sWhh[k][j + 32] * hk;
            hn += sWhh[k][j + 64] * hk;
        }

        r = fsigmoid(r);
        z = fsigmoid(z);
        float n = tanhf(xn + r * hn);
        h = n + z * (h - n);

        ob[(size_t)t * 2 * HH] = h;
    }
}

// ---------------------------------------------------------------------------
// Layer 1: input = g_h1 (K=64). Input projection fused into the recurrence.
// grid: (B/8, 2), block: 256
// ---------------------------------------------------------------------------
__global__ void __launch_bounds__(256) gru_l1_kernel(
    const float* __restrict__ w_ih,   // [2,96,64]
    const float* __restrict__ w_hh,   // [2,96,32]
    const float* __restrict__ b_ih,   // [2,96]
    const float* __restrict__ b_hh)   // [2,96]
{
    __shared__ float sWih[2 * HH][GG];  // transposed: sWih[k][g], k in [0,64)
    __shared__ float sWhh[HH][GG];
    __shared__ float sB[2 * GG];

    const int dir = blockIdx.y;
    const int tid = threadIdx.x;

    const float* wih = w_ih + dir * GG * 2 * HH;
    for (int idx = tid; idx < GG * 2 * HH; idx += 256) {
        int g = idx / (2 * HH), k = idx % (2 * HH);
        sWih[k][g] = wih[idx];
    }
    const float* whh = w_hh + dir * GG * HH;
    for (int idx = tid; idx < GG * HH; idx += 256) {
        int g = idx / HH, k = idx % HH;
        sWhh[k][g] = whh[idx];
    }
    for (int idx = tid; idx < GG; idx += 256) {
        sB[idx]      = b_ih[dir * GG + idx];
        sB[GG + idx] = b_hh[dir * GG + idx];
    }
    __syncthreads();

    const int warp = tid >> 5;
    const int j    = tid & 31;
    const int b    = blockIdx.x * 8 + warp;

    const float br  = sB[j]      + sB[GG + j];
    const float bz  = sB[32 + j] + sB[GG + 32 + j];
    const float bxn = sB[64 + j];
    const float bhn = sB[GG + 64 + j];

    float h = 0.0f;
    const int tstart = dir ? (TT - 1) : 0;
    const int tstep  = dir ? -1 : 1;

    const float* ib = g_h1 + (size_t)b * TT * 2 * HH;
    float* ob = g_out + (size_t)b * TT * 2 * HH + dir * HH + j;

    int t = tstart;
    for (int s = 0; s < TT; ++s, t += tstep) {
        const float* ip = ib + (size_t)t * 2 * HH;
        float a = ip[j];
        float c = ip[j + 32];

        float r  = br;
        float z  = bz;
        float xn = bxn;
        float hn = bhn;

        #pragma unroll
        for (int k = 0; k < 32; k++) {
            float xk = __shfl_sync(0xffffffffu, a, k);
            r  += sWih[k][j]      * xk;
            z  += sWih[k][j + 32] * xk;
            xn += sWih[k][j + 64] * xk;
        }
        #pragma unroll
        for (int k = 0; k < 32; k++) {
            float xk = __shfl_sync(0xffffffffu, c, k);
            r  += sWih[32 + k][j]      * xk;
            z  += sWih[32 + k][j + 32] * xk;
            xn += sWih[32 + k][j + 64] * xk;
        }
        #pragma unroll
        for (int k = 0; k < HH; k++) {
            float hk = __shfl_sync(0xffffffffu, h, k);
            r  += sWhh[k][j]      * hk;
            z  += sWhh[k][j + 32] * hk;
            hn += sWhh[k][j + 64] * hk;
        }

        r = fsigmoid(r);
        z = fsigmoid(z);
        float n = tanhf(xn + r * hn);
        h = n + z * (h - n);

        ob[(size_t)t * 2 * HH] = h;
    }
}

// ---------------------------------------------------------------------------
// Epilogue: attention-softmax pooling over T + sigmoid FC. One block per batch.
// ---------------------------------------------------------------------------
__global__ void __launch_bounds__(256) attn_fc_kernel(
    const float* __restrict__ attn_w,  // [1,64]
    const float* __restrict__ fc_w,    // [1,64]
    const float* __restrict__ fc_b,    // [1]
    float* __restrict__ y)             // [B,1]
{
    __shared__ float sl[TT];
    __shared__ float saw[64], sfw[64];
    __shared__ float redm[8], reds[8];
    __shared__ float sctx[64];

    const int b    = blockIdx.x;
    const int tid  = threadIdx.x;
    const int warp = tid >> 5;
    const int lane = tid & 31;

    if (tid < 64) {
        saw[tid]  = attn_w[tid];
        sfw[tid]  = fc_w[tid];
        sctx[tid] = 0.0f;
    }
    __syncthreads();

    const float* ob = g_out + (size_t)b * TT * 64;

    // logits (attn_b constant over T -> cancels in softmax)
    for (int t = warp; t < TT; t += 8) {
        const float* p = ob + (size_t)t * 64;
        float v = p[lane] * saw[lane] + p[lane + 32] * saw[lane + 32];
        #pragma unroll
        for (int o = 16; o; o >>= 1) v += __shfl_xor_sync(0xffffffffu, v, o);
        if (lane == 0) sl[t] = v;
    }
    __syncthreads();

    // max
    float m = -INFINITY;
    for (int t = tid; t < TT; t += 256) m = fmaxf(m, sl[t]);
    #pragma unroll
    for (int o = 16; o; o >>= 1) m = fmaxf(m, __shfl_xor_sync(0xffffffffu, m, o));
    if (lane == 0) redm[warp] = m;
    __syncthreads();
    float mm = redm[0];
    #pragma unroll
    for (int w = 1; w < 8; w++) mm = fmaxf(mm, redm[w]);

    // exp + sum
    float ssum = 0.0f;
    for (int t = tid; t < TT; t += 256) {
        float p = __expf(sl[t] - mm);
        sl[t] = p;
        ssum += p;
    }
    #pragma unroll
    for (int o = 16; o; o >>= 1) ssum += __shfl_xor_sync(0xffffffffu, ssum, o);
    if (lane == 0) reds[warp] = ssum;
    __syncthreads();

    // ctx accumulation (unnormalized)
    float c0 = 0.0f, c1 = 0.0f;
    for (int t = warp; t < TT; t += 8) {
        float p = sl[t];
        const float* q = ob + (size_t)t * 64;
        c0 += p * q[lane];
        c1 += p * q[lane + 32];
    }
    atomicAdd(&sctx[lane], c0);
    atomicAdd(&sctx[lane + 32], c1);
    __syncthreads();

    if (tid < 32) {
        float Z = reds[0];
        #pragma unroll
        for (int w = 1; w < 8; w++) Z += reds[w];
        float v = sctx[lane] * sfw[lane] + sctx[lane + 32] * sfw[lane + 32];
        #pragma unroll
        for (int o = 16; o; o >>= 1) v += __shfl_xor_sync(0xffffffffu, v, o);
        if (lane == 0) {
            y[b] = 1.0f / (1.0f + __expf(-(v / Z + fc_b[0])));
        }
    }
}

extern "C" void kernel_launch(void* const* d_in, const int* in_sizes, int n_in,
                              void* d_out, int out_size) {
    const float* x       = (const float*)d_in[0];
    const float* w_ih_l0 = (const float*)d_in[1];
    const float* w_hh_l0 = (const float*)d_in[2];
    const float* b_ih_l0 = (const float*)d_in[3];
    const float* b_hh_l0 = (const float*)d_in[4];
    const float* w_ih_l1 = (const float*)d_in[5];
    const float* w_hh_l1 = (const float*)d_in[6];
    const float* b_ih_l1 = (const float*)d_in[7];
    const float* b_hh_l1 = (const float*)d_in[8];
    const float* attn_w  = (const float*)d_in[9];
    // d_in[10] = attn_b (cancels in softmax)
    const float* fc_w    = (const float*)d_in[11];
    const float* fc_b    = (const float*)d_in[12];
    float* y = (float*)d_out;

    dim3 grid(BB / 8, 2);
    gru_l0_kernel<<<grid, 256>>>(x, w_ih_l0, w_hh_l0, b_ih_l0, b_hh_l0);
    gru_l1_kernel<<<grid, 256>>>(w_ih_l1, w_hh_l1, b_ih_l1, b_hh_l1);
    attn_fc_kernel<<<BB, 256>>>(attn_w, fc_w, fc_b, y);
}

// round 2
// speedup vs baseline: 1.0018x; 1.0018x over previous
#include <cuda_runtime.h>
#include <math.h>

#define BB 1024
#define TT 512
#define II 4
#define HH 32
#define GG 96   // 3*H

// Scratch sequence buffers (allocation-free rule: __device__ globals).
__device__ float g_h1 [(size_t)BB * TT * 2 * HH];  // layer0 output, concat [fwd|bwd]
__device__ float g_out[(size_t)BB * TT * 2 * HH];  // layer1 output, concat [fwd|bwd]

__device__ __forceinline__ float fsigmoid(float x) {
    return 1.0f / (1.0f + __expf(-x));
}

// ---------------------------------------------------------------------------
// Layer 0: input I=4. One warp per (batch, dir). Lane j owns hidden dim j.
// grid: (B/8, 2), block: 256 (8 warps)
// ---------------------------------------------------------------------------
__global__ void __launch_bounds__(256) gru_l0_kernel(
    const float* __restrict__ x,      // [B,T,4]
    const float* __restrict__ w_ih,   // [2,96,4]
    const float* __restrict__ w_hh,   // [2,96,32]
    const float* __restrict__ b_ih,   // [2,96]
    const float* __restrict__ b_hh)   // [2,96]
{
    __shared__ float sWhh[HH][GG];   // transposed: sWhh[k][g]
    __shared__ float sB[2 * GG];

    const int dir = blockIdx.y;
    const int tid = threadIdx.x;

    const float* whh = w_hh + dir * GG * HH;
    for (int idx = tid; idx < GG * HH; idx += 256) {
        int g = idx / HH, k = idx % HH;
        sWhh[k][g] = whh[idx];
    }
    for (int idx = tid; idx < GG; idx += 256) {
        sB[idx]      = b_ih[dir * GG + idx];
        sB[GG + idx] = b_hh[dir * GG + idx];
    }
    __syncthreads();

    const int warp = tid >> 5;
    const int j    = tid & 31;
    const int b    = blockIdx.x * 8 + warp;

    // per-thread input-projection weights (12 regs)
    const float* wih = w_ih + dir * GG * II;
    float wr0 = wih[(j     ) * 4 + 0], wr1 = wih[(j     ) * 4 + 1],
          wr2 = wih[(j     ) * 4 + 2], wr3 = wih[(j     ) * 4 + 3];
    float wz0 = wih[(j + 32) * 4 + 0], wz1 = wih[(j + 32) * 4 + 1],
          wz2 = wih[(j + 32) * 4 + 2], wz3 = wih[(j + 32) * 4 + 3];
    float wn0 = wih[(j + 64) * 4 + 0], wn1 = wih[(j + 64) * 4 + 1],
          wn2 = wih[(j + 64) * 4 + 2], wn3 = wih[(j + 64) * 4 + 3];

    const float br  = sB[j]      + sB[GG + j];
    const float bz  = sB[32 + j] + sB[GG + 32 + j];
    const float bxn = sB[64 + j];
    const float bhn = sB[GG + 64 + j];

    float h = 0.0f;
    const int tstart = dir ? (TT - 1) : 0;
    const int tstep  = dir ? -1 : 1;

    const float* xb = x + (size_t)b * TT * II;
    float* ob = g_h1 + (size_t)b * TT * 2 * HH + dir * HH + j;

    int t = tstart;
    for (int s = 0; s < TT; ++s, t += tstep) {
        float4 xx = __ldg(reinterpret_cast<const float4*>(xb + (size_t)t * 4));

        float r  = br  + wr0 * xx.x + wr1 * xx.y + wr2 * xx.z + wr3 * xx.w;
        float z  = bz  + wz0 * xx.x + wz1 * xx.y + wz2 * xx.z + wz3 * xx.w;
        float xn = bxn + wn0 * xx.x + wn1 * xx.y + wn2 * xx.z + wn3 * xx.w;
        float hn = bhn;

        #pragma unroll
        for (int k = 0; k < HH; k++) {
            float hk = __shfl_sync(0xffffffffu, h, k);
            r  += sWhh[k][j]      * hk;
            z  += sWhh[k][j + 32] * hk;
            hn += sWhh[k][j + 64] * hk;
        }

        r = fsigmoid(r);
        z = fsigmoid(z);
        float n = tanhf(xn + r * hn);
        h = n + z * (h - n);

        ob[(size_t)t * 2 * HH] = h;
    }
}

// ---------------------------------------------------------------------------
// Layer 1: input = g_h1 (K=64). Input projection fused into the recurrence.
// grid: (B/8, 2), block: 256
// ---------------------------------------------------------------------------
__global__ void __launch_bounds__(256) gru_l1_kernel(
    const float* __restrict__ w_ih,   // [2,96,64]
    const float* __restrict__ w_hh,   // [2,96,32]
    const float* __restrict__ b_ih,   // [2,96]
    const float* __restrict__ b_hh)   // [2,96]
{
    __shared__ float sWih[2 * HH][GG];  // transposed: sWih[k][g], k in [0,64)
    __shared__ float sWhh[HH][GG];
    __shared__ float sB[2 * GG];

    const int dir = blockIdx.y;
    const int tid = threadIdx.x;

    const float* wih = w_ih + dir * GG * 2 * HH;
    for (int idx = tid; idx < GG * 2 * HH; idx += 256) {
        int g = idx / (2 * HH), k = idx % (2 * HH);
        sWih[k][g] = wih[idx];
    }
    const float* whh = w_hh + dir * GG * HH;
    for (int idx = tid; idx < GG * HH; idx += 256) {
        int g = idx / HH, k = idx % HH;
        sWhh[k][g] = whh[idx];
    }
    for (int idx = tid; idx < GG; idx += 256) {
        sB[idx]      = b_ih[dir * GG + idx];
        sB[GG + idx] = b_hh[dir * GG + idx];
    }
    __syncthreads();

    const int warp = tid >> 5;
    const int j    = tid & 31;
    const int b    = blockIdx.x * 8 + warp;

    const float br  = sB[j]      + sB[GG + j];
    const float bz  = sB[32 + j] + sB[GG + 32 + j];
    const float bxn = sB[64 + j];
    const float bhn = sB[GG + 64 + j];

    float h = 0.0f;
    const int tstart = dir ? (TT - 1) : 0;
    const int tstep  = dir ? -1 : 1;

    const float* ib = g_h1 + (size_t)b * TT * 2 * HH;
    float* ob = g_out + (size_t)b * TT * 2 * HH + dir * HH + j;

    int t = tstart;
    for (int s = 0; s < TT; ++s, t += tstep) {
        const float* ip = ib + (size_t)t * 2 * HH;
        float a = ip[j];
        float c = ip[j + 32];

        float r  = br;
        float z  = bz;
        float xn = bxn;
        float hn = bhn;

        #pragma unroll
        for (int k = 0; k < 32; k++) {
            float xk = __shfl_sync(0xffffffffu, a, k);
            r  += sWih[k][j]      * xk;
            z  += sWih[k][j + 32] * xk;
            xn += sWih[k][j + 64] * xk;
        }
        #pragma unroll
        for (int k = 0; k < 32; k++) {
            float xk = __shfl_sync(0xffffffffu, c, k);
            r  += sWih[32 + k][j]      * xk;
            z  += sWih[32 + k][j + 32] * xk;
            xn += sWih[32 + k][j + 64] * xk;
        }
        #pragma unroll
        for (int k = 0; k < HH; k++) {
            float hk = __shfl_sync(0xffffffffu, h, k);
            r  += sWhh[k][j]      * hk;
            z  += sWhh[k][j + 32] * hk;
            hn += sWhh[k][j + 64] * hk;
        }

        r = fsigmoid(r);
        z = fsigmoid(z);
        float n = tanhf(xn + r * hn);
        h = n + z * (h - n);

        ob[(size_t)t * 2 * HH] = h;
    }
}

// ---------------------------------------------------------------------------
// Epilogue: attention-softmax pooling over T + sigmoid FC. One block per batch.
// ---------------------------------------------------------------------------
__global__ void __launch_bounds__(256) attn_fc_kernel(
    const float* __restrict__ attn_w,  // [1,64]
    const float* __restrict__ fc_w,    // [1,64]
    const float* __restrict__ fc_b,    // [1]
    float* __restrict__ y)             // [B,1]
{
    __shared__ float sl[TT];
    __shared__ float saw[64], sfw[64];
    __shared__ float redm[8], reds[8];
    __shared__ float sctx[64];

    const int b    = blockIdx.x;
    const int tid  = threadIdx.x;
    const int warp = tid >> 5;
    const int lane = tid & 31;

    if (tid < 64) {
        saw[tid]  = attn_w[tid];
        sfw[tid]  = fc_w[tid];
        sctx[tid] = 0.0f;
    }
    __syncthreads();

    const float* ob = g_out + (size_t)b * TT * 64;

    // logits (attn_b constant over T -> cancels in softmax)
    for (int t = warp; t < TT; t += 8) {
        const float* p = ob + (size_t)t * 64;
        float v = p[lane] * saw[lane] + p[lane + 32] * saw[lane + 32];
        #pragma unroll
        for (int o = 16; o; o >>= 1) v += __shfl_xor_sync(0xffffffffu, v, o);
        if (lane == 0) sl[t] = v;
    }
    __syncthreads();

    // max
    float m = -INFINITY;
    for (int t = tid; t < TT; t += 256) m = fmaxf(m, sl[t]);
    #pragma unroll
    for (int o = 16; o; o >>= 1) m = fmaxf(m, __shfl_xor_sync(0xffffffffu, m, o));
    if (lane == 0) redm[warp] = m;
    __syncthreads();
    float mm = redm[0];
    #pragma unroll
    for (int w = 1; w < 8; w++) mm = fmaxf(mm, redm[w]);

    // exp + sum
    float ssum = 0.0f;
    for (int t = tid; t < TT; t += 256) {
        float p = __expf(sl[t] - mm);
        sl[t] = p;
        ssum += p;
    }
    #pragma unroll
    for (int o = 16; o; o >>= 1) ssum += __shfl_xor_sync(0xffffffffu, ssum, o);
    if (lane == 0) reds[warp] = ssum;
    __syncthreads();

    // ctx accumulation (unnormalized)
    float c0 = 0.0f, c1 = 0.0f;
    for (int t = warp; t < TT; t += 8) {
        float p = sl[t];
        const float* q = ob + (size_t)t * 64;
        c0 += p * q[lane];
        c1 += p * q[lane + 32];
    }
    atomicAdd(&sctx[lane], c0);
    atomicAdd(&sctx[lane + 32], c1);
    __syncthreads();

    if (tid < 32) {
        float Z = reds[0];
        #pragma unroll
        for (int w = 1; w < 8; w++) Z += reds[w];
        float v = sctx[lane] * sfw[lane] + sctx[lane + 32] * sfw[lane + 32];
        #pragma unroll
        for (int o = 16; o; o >>= 1) v += __shfl_xor_sync(0xffffffffu, v, o);
        if (lane == 0) {
            y[b] = 1.0f / (1.0f + __expf(-(v / Z + fc_b[0])));
        }
    }
}

extern "C" void kernel_launch(void* const* d_in, const int* in_sizes, int n_in,
                              void* d_out, int out_size) {
    const float* x       = (const float*)d_in[0];
    const float* w_ih_l0 = (const float*)d_in[1];
    const float* w_hh_l0 = (const float*)d_in[2];
    const float* b_ih_l0 = (const float*)d_in[3];
    const float* b_hh_l0 = (const float*)d_in[4];
    const float* w_ih_l1 = (const float*)d_in[5];
    const float* w_hh_l1 = (const float*)d_in[6];
    const float* b_ih_l1 = (const float*)d_in[7];
    const float* b_hh_l1 = (const float*)d_in[8];
    const float* attn_w  = (const float*)d_in[9];
    // d_in[10] = attn_b (cancels in softmax)
    const float* fc_w    = (const float*)d_in[11];
    const float* fc_b    = (const float*)d_in[12];
    float* y = (float*)d_out;

    dim3 grid(BB / 8, 2);
    gru_l0_kernel<<<grid, 256>>>(x, w_ih_l0, w_hh_l0, b_ih_l0, b_hh_l0);
    gru_l1_kernel<<<grid, 256>>>(w_ih_l1, w_hh_l1, b_ih_l1, b_hh_l1);
    attn_fc_kernel<<<BB, 256>>>(attn_w, fc_w, fc_b, y);
}